// round 13
// baseline (speedup 1.0000x reference)
#include <cuda_runtime.h>
#include <cuda_fp16.h>
#include <cstdint>

// ---------------- problem constants ----------------
constexpr int Mrows = 16384;          // B*C*T = 4*8*512
constexpr int K512  = 512;

// GEMM tiling: 3 Gauss products per CTA
constexpr int BM = 128, BN = 128, BK = 32;
constexpr int KSTEPS = K512 / BK;     // 16

// smem: rows padded to 40 halves = 80 B — ldmatrix conflict-free (proven R8-R12)
constexpr int ROWB = 80;
constexpr int TILE = 128 * ROWB;      // 10240 (both A and B tiles are 128 rows)
constexpr int STAGE = 9 * TILE;       // 92160: A r,i,s (t=0..2) + B rhi,rlo,ihi,ilo,shi,slo (t=3..8)
constexpr int SMEM_BYTES = 2 * STAGE; // 184320

constexpr size_t VS  = (size_t)Mrows * K512;    // activation variant stride
constexpr size_t WVS = (size_t)K512 * K512;     // weight variant stride

// ---------------- device scratch (allocation-free) ----------------
__device__ __half g_Xh[3][3][Mrows * K512];     // q,k,v activations fp16: r,i,s
__device__ __half g_Ao[3][Mrows * K512];        // attention output fp16: r,i,s (o-GEMM input)
__device__ __half g_Wf[4][6][K512 * K512];      // weights fp16 hi/lo x (r,i,s): q,k,v,o
__device__ float g_bR[4][K512];                 // br - bi
__device__ float g_bI[4][K512];                 // br + bi
__device__ float g_Y[6][Mrows * K512];          // qr,qi,kr,ki,vr,vi (fp32)

// ---------------- PTX helpers (family-portable only) ----------------
#define CP_ASYNC16(dst, src) \
    asm volatile("cp.async.cg.shared.global [%0], [%1], 16;" :: "r"(dst), "l"(src))
#define CP_COMMIT() asm volatile("cp.async.commit_group;")
#define CP_WAIT(n)  asm volatile("cp.async.wait_group %0;" :: "n"(n))

#define LDSM_X4(r0, r1, r2, r3, addr) \
    asm volatile("ldmatrix.sync.aligned.m8n8.x4.shared.b16 {%0,%1,%2,%3}, [%4];" \
        : "=r"(r0), "=r"(r1), "=r"(r2), "=r"(r3) : "r"(addr))

__device__ __forceinline__ void mma_f16(float* d, const uint32_t* a, uint32_t b0, uint32_t b1) {
    asm volatile(
        "mma.sync.aligned.m16n8k16.row.col.f32.f16.f16.f32 "
        "{%0,%1,%2,%3}, {%4,%5,%6,%7}, {%8,%9}, {%0,%1,%2,%3};"
        : "+f"(d[0]), "+f"(d[1]), "+f"(d[2]), "+f"(d[3])
        : "r"(a[0]), "r"(a[1]), "r"(a[2]), "r"(a[3]), "r"(b0), "r"(b1));
}

// ============================================================================
// pack weights: Wr, Wi, Ws=Wr+Wi as fp16 hi/lo; biases br-bi, br+bi
// ============================================================================
__global__ void pack_f(const float* __restrict__ Wr, const float* __restrict__ Wi,
                       const float* __restrict__ br, const float* __restrict__ bi,
                       __half* __restrict__ W6, float* __restrict__ bR,
                       float* __restrict__ bI)
{
    int idx = blockIdx.x * 256 + threadIdx.x;     // over 262144
    float vr = Wr[idx], vi = Wi[idx], vs = vr + vi;
    float vals[3] = {vr, vi, vs};
#pragma unroll
    for (int p = 0; p < 3; p++) {
        __half h = __float2half(vals[p]);
        W6[(size_t)(2 * p) * WVS + idx] = h;
        W6[(size_t)(2 * p + 1) * WVS + idx] = __float2half(vals[p] - __half2float(h));
    }
    if (idx < K512) {
        bR[idx] = br[idx] - bi[idx];
        bI[idx] = br[idx] + bi[idx];
    }
}

// ============================================================================
// split fp32 inputs into single fp16 for r, i, s=r+i
// ============================================================================
struct alignas(8) HF4 { __half v[4]; };

__global__ void split_f(const float* __restrict__ xr, const float* __restrict__ xi,
                        __half* __restrict__ X)
{
    size_t i4 = (size_t)(blockIdx.x * 256 + threadIdx.x) * 4;
    float4 vr = *(const float4*)(xr + i4);
    float4 vi = *(const float4*)(xi + i4);
    float ar[4] = {vr.x, vr.y, vr.z, vr.w};
    float ai[4] = {vi.x, vi.y, vi.z, vi.w};
    HF4 out[3];
#pragma unroll
    for (int j = 0; j < 4; j++) {
        out[0].v[j] = __float2half(ar[j]);
        out[1].v[j] = __float2half(ai[j]);
        out[2].v[j] = __float2half(ar[j] + ai[j]);
    }
#pragma unroll
    for (int v = 0; v < 3; v++)
        *(HF4*)(X + (size_t)v * VS + i4) = out[v];
}

// ============================================================================
// Fused Gauss GEMM: per CTA compute P1,P2,P3 for its 128x128 tile and emit
//   Yr = P1 - P2 + bR,  Yi = P3 - P1 - P2 + bI   (optional lrelu)
// P_p = A_p @ (W_p_hi + W_p_lo)^T, fp16 operands, fp32 accum.
// mode 0: QKV (z = layer; out = g_Y[2z],g_Y[2z+1]; lrelu for z==2)
// mode 1: o layer (out = outR/outI = d_out halves)
// 512 threads, 4x4 warps, warp tile 32x32, double-buffered cp.async.
// ============================================================================
__global__ void __launch_bounds__(512, 1)
gemm_y(int mode, float* __restrict__ outR, float* __restrict__ outI)
{
    const int z = blockIdx.z;
    const __half* A0;                // variant p at A0 + p*VS
    const __half* W0;                // variant v at W0 + v*WVS
    const float *bR, *bI;
    float *oR, *oI;
    int lrelu;
    if (mode == 0) {
        A0 = g_Xh[z][0];
        W0 = g_Wf[z][0];
        bR = g_bR[z]; bI = g_bI[z];
        oR = g_Y[2 * z]; oI = g_Y[2 * z + 1];
        lrelu = (z == 2);
    } else {
        A0 = g_Ao[0];
        W0 = g_Wf[3][0];
        bR = g_bR[3]; bI = g_bI[3];
        oR = outR; oI = outI;
        lrelu = 0;
    }

    extern __shared__ char smem[];
    const int tid = threadIdx.x;
    const int wid = tid >> 5, lane = tid & 31;
    const int wm = wid >> 2, wn = wid & 3;        // 4 x 4 warps, warp tile 32 x 32
    const int r = lane >> 2, c = lane & 3;
    const int bm = blockIdx.x * BM, bn = blockIdx.y * BN;

    const uint32_t sb = (uint32_t)__cvta_generic_to_shared(smem);

    // ldmatrix per-lane offsets (proven pattern)
    const int arow = (lane & 7) + ((lane >> 3) & 1) * 8;
    const int akof = ((lane >> 4) & 1) * 16;
    const uint32_t a_off = (uint32_t)((wm * 32 + arow) * ROWB + akof);
    const int brow = (lane & 7) + ((lane >> 4) & 1) * 8;
    const int bkof = ((lane >> 3) & 1) * 16;
    const uint32_t b_off = (uint32_t)((wn * 32 + brow) * ROWB + bkof);

    float acc[3][2][4][4];                        // [product][mi][nj][e]
#pragma unroll
    for (int p = 0; p < 3; p++)
#pragma unroll
        for (int mi = 0; mi < 2; mi++)
#pragma unroll
            for (int nj = 0; nj < 4; nj++)
#pragma unroll
                for (int e = 0; e < 4; e++) acc[p][mi][nj][e] = 0.f;

    // loader: 9 tiles x 512 cp.async16 = 1 per thread per tile
    const int lrow = tid >> 2, lch = tid & 3;
    auto load_stage = [&](int s, int kt) {
        uint32_t base = sb + s * STAGE;
        size_t acol = kt + lch * 8;
#pragma unroll
        for (int t = 0; t < 3; t++)
            CP_ASYNC16(base + t * TILE + lrow * ROWB + lch * 16,
                       A0 + (size_t)t * VS + (size_t)(bm + lrow) * K512 + acol);
#pragma unroll
        for (int t = 0; t < 6; t++)
            CP_ASYNC16(base + (3 + t) * TILE + lrow * ROWB + lch * 16,
                       W0 + (size_t)t * WVS + (size_t)(bn + lrow) * K512 + acol);
        CP_COMMIT();
    };

    load_stage(0, 0);

    for (int s = 0; s < KSTEPS; s++) {
        if (s + 1 < KSTEPS) {
            load_stage((s + 1) & 1, (s + 1) * BK);
            CP_WAIT(1);
        } else {
            CP_WAIT(0);
        }
        __syncthreads();

        const uint32_t stb = sb + (s & 1) * STAGE;
#pragma unroll
        for (int kk = 0; kk < 2; kk++) {
            const uint32_t kb = stb + kk * 32;
#pragma unroll
            for (int p = 0; p < 3; p++) {
                uint32_t ah[2][4];
#pragma unroll
                for (int mi = 0; mi < 2; mi++)
                    LDSM_X4(ah[mi][0], ah[mi][1], ah[mi][2], ah[mi][3],
                            kb + p * TILE + a_off + mi * (16 * ROWB));
#pragma unroll
                for (int g = 0; g < 2; g++) {
                    uint32_t bh[4], bl[4];
                    LDSM_X4(bh[0], bh[1], bh[2], bh[3],
                            kb + (3 + 2 * p) * TILE + b_off + g * (16 * ROWB));
                    LDSM_X4(bl[0], bl[1], bl[2], bl[3],
                            kb + (3 + 2 * p + 1) * TILE + b_off + g * (16 * ROWB));
#pragma unroll
                    for (int mi = 0; mi < 2; mi++) {
                        mma_f16(acc[p][mi][2 * g + 0], ah[mi], bh[0], bh[1]);
                        mma_f16(acc[p][mi][2 * g + 0], ah[mi], bl[0], bl[1]);
                        mma_f16(acc[p][mi][2 * g + 1], ah[mi], bh[2], bh[3]);
                        mma_f16(acc[p][mi][2 * g + 1], ah[mi], bl[2], bl[3]);
                    }
                }
            }
        }
        __syncthreads();
    }

    // ---- epilogue: Gauss combine + bias + optional lrelu, write Yr & Yi ----
#pragma unroll
    for (int mi = 0; mi < 2; mi++) {
#pragma unroll
        for (int nj = 0; nj < 4; nj++) {
            int ncol = bn + wn * 32 + nj * 8 + 2 * c;
            float br0 = bR[ncol], br1 = bR[ncol + 1];
            float bi0 = bI[ncol], bi1 = bI[ncol + 1];
            int row0 = bm + wm * 32 + mi * 16 + r;
#pragma unroll
            for (int hrow = 0; hrow < 2; hrow++) {
                float p1a = acc[0][mi][nj][2 * hrow + 0], p1b = acc[0][mi][nj][2 * hrow + 1];
                float p2a = acc[1][mi][nj][2 * hrow + 0], p2b = acc[1][mi][nj][2 * hrow + 1];
                float p3a = acc[2][mi][nj][2 * hrow + 0], p3b = acc[2][mi][nj][2 * hrow + 1];
                float yr0 = p1a - p2a + br0, yr1 = p1b - p2b + br1;
                float yi0 = p3a - p1a - p2a + bi0, yi1 = p3b - p1b - p2b + bi1;
                if (lrelu) {
                    yr0 = yr0 >= 0.f ? yr0 : 0.01f * yr0;
                    yr1 = yr1 >= 0.f ? yr1 : 0.01f * yr1;
                    yi0 = yi0 >= 0.f ? yi0 : 0.01f * yi0;
                    yi1 = yi1 >= 0.f ? yi1 : 0.01f * yi1;
                }
                size_t o = (size_t)(row0 + 8 * hrow) * K512 + ncol;
                *(float2*)&oR[o] = make_float2(yr0, yr1);
                *(float2*)&oI[o] = make_float2(yi0, yi1);
            }
        }
    }
}

// ============================================================================
// channel attention: per (b,h,t) 8x8 complex scores (no softmax), S@V, lrelu,
// reads qr..vi (g_Y fp32), writes o-GEMM input splits g_Ao (fp16 r,i,s)
// ============================================================================
__global__ void attn_kernel()
{
    __shared__ float sm[6][8][68];
    __shared__ float ssr[8][9], ssi[8][9];

    const int t = blockIdx.x, h = blockIdx.y, b = blockIdx.z;
    const int tid = threadIdx.x;

    {
        int cch = tid >> 4, d4 = (tid & 15) << 2;
        size_t base = (((size_t)(b * 8 + cch) * 512 + t) * 512) + h * 64 + d4;
#pragma unroll
        for (int v = 0; v < 6; v++)
            *(float4*)&sm[v][cch][d4] = *(const float4*)&g_Y[v][base];
    }
    __syncthreads();

    if (tid < 64) {
        int cc = tid >> 3, e = tid & 7;
        float ar = 0.f, ai = 0.f;
#pragma unroll 8
        for (int d = 0; d < 64; d++) {
            float qr = sm[0][cc][d], qi = sm[1][cc][d];
            float kr = sm[2][e][d],  ki = sm[3][e][d];
            ar = fmaf(qr, kr, fmaf(qi, ki, ar));
            ai = fmaf(qr, ki, fmaf(-qi, kr, ai));
        }
        ssr[cc][e] = ar * 0.125f;
        ssi[cc][e] = ai * 0.125f;
    }
    __syncthreads();

#pragma unroll
    for (int i = 0; i < 4; i++) {
        int idx = tid + i * 128;
        int cc = idx >> 6, d = idx & 63;
        float xr = 0.f, xi = 0.f;
#pragma unroll
        for (int e = 0; e < 8; e++) {
            float sr_ = ssr[cc][e], si_ = ssi[cc][e];
            float vr = sm[4][e][d], vi = sm[5][e][d];
            xr = fmaf(sr_, vr, fmaf(-si_, vi, xr));
            xi = fmaf(si_, vr, fmaf(sr_, vi, xi));
        }
        xr = xr >= 0.f ? xr : 0.01f * xr;
        xi = xi >= 0.f ? xi : 0.01f * xi;
        size_t mrow = (size_t)(b * 8 + cc) * 512 + t;
        size_t o = mrow * K512 + h * 64 + d;
        g_Ao[0][o] = __float2half(xr);
        g_Ao[1][o] = __float2half(xi);
        g_Ao[2][o] = __float2half(xr + xi);
    }
}

// ============================================================================
// host side: pack x4, split x3, gemm_y(QKV), attn, gemm_y(o -> d_out)
// ============================================================================
extern "C" void kernel_launch(void* const* d_in, const int* in_sizes, int n_in,
                              void* d_out, int out_size)
{
    const float* in[22];
    for (int i = 0; i < 22; i++) in[i] = (const float*)d_in[i];

    void *Xh_, *Wf_, *bR_, *bI_;
    cudaGetSymbolAddress(&Xh_, g_Xh);
    cudaGetSymbolAddress(&Wf_, g_Wf);
    cudaGetSymbolAddress(&bR_, g_bR);
    cudaGetSymbolAddress(&bI_, g_bI);

    __half* Xh = (__half*)Xh_;
    __half* Wf = (__half*)Wf_;
    float* bR = (float*)bR_;
    float* bI = (float*)bI_;

    cudaFuncSetAttribute(gemm_y, cudaFuncAttributeMaxDynamicSharedMemorySize, SMEM_BYTES);

    // weights: 6=Wq_r 7=bq_r 8=Wq_i 9=bq_i | 10..13 k | 14..17 v | 18..21 o
    pack_f<<<1024, 256>>>(in[6],  in[8],  in[7],  in[9],  Wf + 0 * 6 * WVS, bR + 0 * K512, bI + 0 * K512);
    pack_f<<<1024, 256>>>(in[10], in[12], in[11], in[13], Wf + 1 * 6 * WVS, bR + 1 * K512, bI + 1 * K512);
    pack_f<<<1024, 256>>>(in[14], in[16], in[15], in[17], Wf + 2 * 6 * WVS, bR + 2 * K512, bI + 2 * K512);
    pack_f<<<1024, 256>>>(in[18], in[20], in[19], in[21], Wf + 3 * 6 * WVS, bR + 3 * K512, bI + 3 * K512);

    // input splits (q, k, v) -> fp16 r,i,s
    split_f<<<8192, 256>>>(in[0], in[1], Xh + 0 * 3 * VS);
    split_f<<<8192, 256>>>(in[2], in[3], Xh + 1 * 3 * VS);
    split_f<<<8192, 256>>>(in[4], in[5], Xh + 2 * 3 * VS);

    // QKV: 3 layers, each CTA does all 3 Gauss products -> writes qr..vi
    gemm_y<<<dim3(Mrows / BM, K512 / BN, 3), 512, SMEM_BYTES>>>(0, nullptr, nullptr);

    // attention
    attn_kernel<<<dim3(512, 8, 4), 128>>>();

    // o layer: writes d_out directly (Yr | Yi)
    float* outR = (float*)d_out;
    float* outI = outR + (size_t)Mrows * K512;
    gemm_y<<<dim3(Mrows / BM, K512 / BN, 1), 512, SMEM_BYTES>>>(1, outR, outI);
}